// round 1
// baseline (speedup 1.0000x reference)
#include <cuda_runtime.h>
#include <math.h>

// ---------------------------------------------------------------------------
// GCN(2 layer) -> node-0 embedding -> 1-step LSTM -> FC -> scalar.
// Key insight: output depends only on the 2-hop in-neighborhood of node 0.
// S1 = in-neighbors of node 0 (~32 nodes), S2 = in-neighbors of S1 (~1100).
// We discover S1/S2 with streaming passes over dst[], count degrees only for
// flagged nodes, and run the dense math on ~1100 nodes instead of 100K.
// ---------------------------------------------------------------------------

#define NN_MAX   100000
#define IND      128
#define H        64
#define S1CAP    4096
#define E0CAP    4096
#define ECAP     32768
#define BMWORDS  ((NN_MAX + 31) / 32)

static __device__ int      g_deg[NN_MAX];
static __device__ int      g_flag1[NN_MAX];   // pos+1 in S1 list (0 = not member)
static __device__ int      g_flag2[NN_MAX];   // pos+1 in S2 list
static __device__ unsigned g_bm1[BMWORDS];    // membership bitmap for S1
static __device__ unsigned g_bm2[BMWORDS];    // membership bitmap for S2
static __device__ int      g_s1[S1CAP];       // unique S1 node ids
static __device__ int      g_e0[E0CAP];       // src of every edge with dst==0 (multiplicity kept)
static __device__ int      g_s2[ECAP];        // unique S2 node ids
static __device__ int2     g_e1[ECAP];        // (src, dst) for every edge with dst in S1
static __device__ int      g_cnt1, g_cnt2, g_cntE0, g_cntE1;
static __device__ float    g_hlin[ECAP][H];   // x[:,u] @ W1 for u in S2
static __device__ float    g_acc1[S1CAP][H];  // layer-1 aggregation for S1 nodes
static __device__ float    g_h2[S1CAP][H];    // relu(acc1+b1) @ W2

// ---------------------------------------------------------------------------
__global__ void k_init(int n) {
    int i = blockIdx.x * blockDim.x + threadIdx.x;
    if (i < n) {
        g_deg[i]   = 0;
        g_flag1[i] = (i == 0) ? 1 : 0;
        g_flag2[i] = (i == 0) ? 1 : 0;
    }
    if (i < BMWORDS) {
        g_bm1[i] = (i == 0) ? 1u : 0u;
        g_bm2[i] = (i == 0) ? 1u : 0u;
    }
    if (i == 0) {
        g_cnt1 = 1; g_cnt2 = 1; g_cntE0 = 0; g_cntE1 = 0;
        g_s1[0] = 0; g_s2[0] = 0;
    }
}

// ---------------------------------------------------------------------------
// Pass 1: find all edges with dst == 0; build unique S1 (also inserted in S2).
__device__ __forceinline__ void scan1_one(const int* __restrict__ src, int d, int idx) {
    if (d == 0) {
        int s = src[idx];
        int p = atomicAdd(&g_cntE0, 1);
        if (p < E0CAP) g_e0[p] = s;
        if (atomicCAS(&g_flag1[s], 0, -1) == 0) {
            int q = atomicAdd(&g_cnt1, 1);
            if (q < S1CAP) g_s1[q] = s;
            g_flag1[s] = q + 1;
            atomicOr(&g_bm1[s >> 5], 1u << (s & 31));
            // S1 nodes also need hlin (self loop) -> member of S2
            if (atomicCAS(&g_flag2[s], 0, -1) == 0) {
                int r = atomicAdd(&g_cnt2, 1);
                if (r < ECAP) g_s2[r] = s;
                g_flag2[s] = r + 1;
                atomicOr(&g_bm2[s >> 5], 1u << (s & 31));
            }
        }
    }
}

__global__ void k_scan1(const int* __restrict__ src, const int* __restrict__ dst, int E) {
    int tid = blockIdx.x * blockDim.x + threadIdx.x;
    int nt  = gridDim.x * blockDim.x;
    int E4  = E >> 2;
    const int4* dst4 = (const int4*)dst;
    for (int i = tid; i < E4; i += nt) {
        int4 v = dst4[i];
        scan1_one(src, v.x, 4 * i + 0);
        scan1_one(src, v.y, 4 * i + 1);
        scan1_one(src, v.z, 4 * i + 2);
        scan1_one(src, v.w, 4 * i + 3);
    }
    for (int i = E4 * 4 + tid; i < E; i += nt) scan1_one(src, dst[i], i);
}

// ---------------------------------------------------------------------------
// Pass 2: edges with dst in S1 -> E1 list; build unique S2.
__device__ __forceinline__ void scan2_one(const int* __restrict__ src, int d, int idx) {
    if ((g_bm1[d >> 5] >> (d & 31)) & 1u) {
        int s = src[idx];
        int p = atomicAdd(&g_cntE1, 1);
        if (p < ECAP) g_e1[p] = make_int2(s, d);
        if (atomicCAS(&g_flag2[s], 0, -1) == 0) {
            int r = atomicAdd(&g_cnt2, 1);
            if (r < ECAP) g_s2[r] = s;
            g_flag2[s] = r + 1;
            atomicOr(&g_bm2[s >> 5], 1u << (s & 31));
        }
    }
}

__global__ void k_scan2(const int* __restrict__ src, const int* __restrict__ dst, int E) {
    int tid = blockIdx.x * blockDim.x + threadIdx.x;
    int nt  = gridDim.x * blockDim.x;
    int E4  = E >> 2;
    const int4* dst4 = (const int4*)dst;
    for (int i = tid; i < E4; i += nt) {
        int4 v = dst4[i];
        scan2_one(src, v.x, 4 * i + 0);
        scan2_one(src, v.y, 4 * i + 1);
        scan2_one(src, v.z, 4 * i + 2);
        scan2_one(src, v.w, 4 * i + 3);
    }
    for (int i = E4 * 4 + tid; i < E; i += nt) scan2_one(src, dst[i], i);
}

// ---------------------------------------------------------------------------
// Pass 3: in-degree for flagged (S2) nodes only. Bitmap is 12.5KB -> L1-hot.
__global__ void k_scan3(const int* __restrict__ dst, int E) {
    int tid = blockIdx.x * blockDim.x + threadIdx.x;
    int nt  = gridDim.x * blockDim.x;
    int E4  = E >> 2;
    const int4* dst4 = (const int4*)dst;
    for (int i = tid; i < E4; i += nt) {
        int4 v = dst4[i];
        if ((g_bm2[v.x >> 5] >> (v.x & 31)) & 1u) atomicAdd(&g_deg[v.x], 1);
        if ((g_bm2[v.y >> 5] >> (v.y & 31)) & 1u) atomicAdd(&g_deg[v.y], 1);
        if ((g_bm2[v.z >> 5] >> (v.z & 31)) & 1u) atomicAdd(&g_deg[v.z], 1);
        if ((g_bm2[v.w >> 5] >> (v.w & 31)) & 1u) atomicAdd(&g_deg[v.w], 1);
    }
    for (int i = E4 * 4 + tid; i < E; i += nt) {
        int d = dst[i];
        if ((g_bm2[d >> 5] >> (d & 31)) & 1u) atomicAdd(&g_deg[d], 1);
    }
}

// ---------------------------------------------------------------------------
// hlin[j] = x[:, u] @ W1 for every u in S2. W1 cached in shared (32KB).
__global__ void k_hlin(const float* __restrict__ x, const float* __restrict__ W1, int n) {
    __shared__ float sW[IND * H];
    for (int k = threadIdx.x; k < IND * H; k += blockDim.x) sW[k] = W1[k];
    __syncthreads();
    int t = threadIdx.x;  // 0..63
    int m = min(g_cnt2, ECAP);
    for (int j = blockIdx.x; j < m; j += gridDim.x) {
        int u = g_s2[j];
        float acc = 0.f;
        #pragma unroll 8
        for (int d = 0; d < IND; d++)
            acc += __ldg(&x[(size_t)d * n + u]) * sW[d * H + t];
        g_hlin[j][t] = acc;
    }
}

// ---------------------------------------------------------------------------
// Layer-1 self-loop init: acc1[j] = dinv(u)^2 * hlin[pos2(u)].
__global__ void k_self(void) {
    int t = threadIdx.x;
    int m = min(g_cnt1, S1CAP);
    for (int j = blockIdx.x; j < m; j += gridDim.x) {
        int u  = g_s1[j];
        float di = rsqrtf((float)g_deg[u] + 1.0f);
        int p2 = g_flag2[u] - 1;
        g_acc1[j][t] = di * di * g_hlin[p2][t];
    }
}

// Layer-1 edge scatter into acc1.
__global__ void k_edges(void) {
    int t = threadIdx.x;
    int m = min(g_cntE1, ECAP);
    for (int e = blockIdx.x; e < m; e += gridDim.x) {
        int2 ed = g_e1[e];
        int dp = g_flag1[ed.y] - 1;
        int sp = g_flag2[ed.x] - 1;
        float nrm = rsqrtf((float)g_deg[ed.x] + 1.0f) * rsqrtf((float)g_deg[ed.y] + 1.0f);
        atomicAdd(&g_acc1[dp][t], nrm * g_hlin[sp][t]);
    }
}

// ---------------------------------------------------------------------------
// h1 = relu(acc1 + b1); h2lin = h1 @ W2   (for S1 nodes)
__global__ void k_layer2(const float* __restrict__ b1, const float* __restrict__ W2) {
    __shared__ float sW2[H * H];
    __shared__ float sh[H];
    int t = threadIdx.x;
    for (int k = t; k < H * H; k += blockDim.x) sW2[k] = W2[k];
    __syncthreads();
    int m = min(g_cnt1, S1CAP);
    for (int j = blockIdx.x; j < m; j += gridDim.x) {
        sh[t] = fmaxf(g_acc1[j][t] + b1[t], 0.0f);
        __syncthreads();
        float acc = 0.f;
        #pragma unroll
        for (int h = 0; h < H; h++) acc += sh[h] * sW2[h * H + t];
        g_h2[j][t] = acc;
        __syncthreads();
    }
}

// ---------------------------------------------------------------------------
// Final: z = GCN layer-2 aggregation at node 0 -> LSTM single step -> FC.
__global__ void k_final(const float* __restrict__ b2,
                        const float* __restrict__ w_ih,
                        const float* __restrict__ b_ih,
                        const float* __restrict__ b_hh,
                        const float* __restrict__ fc_w,
                        const float* __restrict__ fc_b,
                        float* __restrict__ out) {
    __shared__ float z[H];
    __shared__ float gates[4 * H];
    __shared__ float red[H];
    int t = threadIdx.x;  // 0..255
    float d0 = rsqrtf((float)g_deg[0] + 1.0f);
    if (t < H) {
        float zv = b2[t] + d0 * d0 * g_h2[0][t];
        int m = min(g_cntE0, E0CAP);
        for (int e = 0; e < m; e++) {
            int s  = g_e0[e];
            int sp = g_flag1[s] - 1;
            zv += rsqrtf((float)g_deg[s] + 1.0f) * d0 * g_h2[sp][t];
        }
        z[t] = zv;
    }
    __syncthreads();
    {
        float a = b_ih[t] + b_hh[t];
        #pragma unroll
        for (int h = 0; h < H; h++) a += w_ih[t * H + h] * z[h];
        gates[t] = a;
    }
    __syncthreads();
    if (t < H) {
        float ig = gates[t];
        float gg = gates[2 * H + t];
        float og = gates[3 * H + t];
        float si = 1.0f / (1.0f + expf(-ig));
        float c  = si * tanhf(gg);
        float so = 1.0f / (1.0f + expf(-og));
        float hy = so * tanhf(c);
        red[t] = hy * fc_w[t];
    }
    __syncthreads();
    if (t == 0) {
        float s = 0.f;
        for (int k = 0; k < H; k++) s += red[k];
        out[0] = s + fc_b[0];
    }
}

// ---------------------------------------------------------------------------
extern "C" void kernel_launch(void* const* d_in, const int* in_sizes, int n_in,
                              void* d_out, int out_size) {
    const float* x    = (const float*)d_in[0];
    const int*   ei   = (const int*)d_in[1];
    const float* W1   = (const float*)d_in[2];
    const float* b1   = (const float*)d_in[3];
    const float* W2   = (const float*)d_in[4];
    const float* b2   = (const float*)d_in[5];
    const float* w_ih = (const float*)d_in[6];
    // d_in[7] = w_hh (unused: h0 = 0)
    const float* b_ih = (const float*)d_in[8];
    const float* b_hh = (const float*)d_in[9];
    const float* fc_w = (const float*)d_in[10];
    const float* fc_b = (const float*)d_in[11];
    float* out = (float*)d_out;

    int N = in_sizes[0] / IND;
    int E = in_sizes[1] / 2;
    const int* src = ei;
    const int* dst = ei + E;

    k_init<<<(N + 255) / 256, 256>>>(N);
    k_scan1<<<1024, 256>>>(src, dst, E);
    k_scan2<<<1024, 256>>>(src, dst, E);
    k_scan3<<<1024, 256>>>(dst, E);
    k_hlin<<<512, H>>>(x, W1, N);
    k_self<<<64, H>>>();
    k_edges<<<256, H>>>();
    k_layer2<<<64, H>>>(b1, W2);
    k_final<<<1, 4 * H>>>(b2, w_ih, b_ih, b_hh, fc_w, fc_b, out);
}

// round 2
// speedup vs baseline: 1.0968x; 1.0968x over previous
#include <cuda_runtime.h>
#include <math.h>

// ---------------------------------------------------------------------------
// Single persistent-kernel implementation.
// Output depends only on 2-hop in-neighborhood of node 0:
//   S1 = in-neighbors of 0 (~32), S2 = in-neighbors of S1 (~1100).
// Phases (separated by software grid barriers, 148 co-resident CTAs):
//   0: init flags/bitmaps/deg/acc
//   1: scan dst for dst==0  -> e0 list, S1 set
//   2: scan dst for dst in S1 -> e1 list, S2 set      (dst now L2-resident)
//   3: scan dst gated by S2 bitmap -> deg ; then hlin = x[:,u] @ W1, u in S2
//   4: layer-1 aggregation into acc1 (self loops + e1 edges, RED atomics)
//   5: h2 = relu(acc1+b1) @ W2 for S1 nodes
//   6: block 0: layer-2 aggregation at node 0 -> LSTM step -> FC -> out
// ---------------------------------------------------------------------------

#define NN_MAX   100000
#define IND      128
#define H        64
#define NB       148
#define NT       512
#define S1CAP    512
#define E0CAP    2048
#define ECAP     32768
#define BMWORDS  ((NN_MAX + 31) / 32)

static __device__ int      g_deg[NN_MAX];
static __device__ int      g_flag1[NN_MAX];   // pos+1 in S1 (0 = not member)
static __device__ int      g_flag2[NN_MAX];   // pos+1 in S2
static __device__ unsigned g_bm1[BMWORDS];
static __device__ unsigned g_bm2[BMWORDS];
static __device__ int      g_s1[S1CAP];
static __device__ int      g_e0[E0CAP];       // src of edges with dst==0 (multiplicity kept)
static __device__ int      g_s2[ECAP];
static __device__ int2     g_e1[ECAP];        // edges with dst in S1
static __device__ int      g_cnt1, g_cnt2, g_cntE0, g_cntE1;
static __device__ float    g_hlin[ECAP][H];
static __device__ float    g_acc1[S1CAP][H];
static __device__ float    g_h2[S1CAP][H];
static __device__ unsigned g_barcnt = 0;
static __device__ unsigned g_sense  = 0;

// Software grid barrier. All-thread __threadfence() (gpu scope) both orders
// plain stores into L2 and emits CCTL.IVALL, invalidating this SM's L1D so
// post-barrier plain loads can't see stale lines (L1 is NOT flushed within a
// launch on sm_103a).
__device__ __forceinline__ void gridbar() {
    __threadfence();
    __syncthreads();
    if (threadIdx.x == 0) {
        unsigned s = atomicAdd(&g_sense, 0u);
        if (atomicAdd(&g_barcnt, 1u) == NB - 1u) {
            atomicExch(&g_barcnt, 0u);
            __threadfence();
            atomicAdd(&g_sense, 1u);
        } else {
            while (atomicAdd(&g_sense, 0u) == s) { }
        }
        __threadfence();
    }
    __syncthreads();
}

__device__ __forceinline__ void scan1_one(const int* __restrict__ src, int d, int idx) {
    if (d == 0) {
        int s = src[idx];
        int p = atomicAdd(&g_cntE0, 1);
        if (p < E0CAP) g_e0[p] = s;
        if (atomicCAS(&g_flag1[s], 0, -1) == 0) {
            int q = atomicAdd(&g_cnt1, 1);
            if (q < S1CAP) g_s1[q] = s;
            g_flag1[s] = q + 1;
            atomicOr(&g_bm1[s >> 5], 1u << (s & 31));
            if (atomicCAS(&g_flag2[s], 0, -1) == 0) {
                int r = atomicAdd(&g_cnt2, 1);
                if (r < ECAP) g_s2[r] = s;
                g_flag2[s] = r + 1;
                atomicOr(&g_bm2[s >> 5], 1u << (s & 31));
            }
        }
    }
}

__device__ __forceinline__ void scan2_one(const int* __restrict__ src, int d, int idx) {
    if ((g_bm1[d >> 5] >> (d & 31)) & 1u) {
        int s = src[idx];
        int p = atomicAdd(&g_cntE1, 1);
        if (p < ECAP) g_e1[p] = make_int2(s, d);
        if (atomicCAS(&g_flag2[s], 0, -1) == 0) {
            int r = atomicAdd(&g_cnt2, 1);
            if (r < ECAP) g_s2[r] = s;
            g_flag2[s] = r + 1;
            atomicOr(&g_bm2[s >> 5], 1u << (s & 31));
        }
    }
}

__device__ __forceinline__ void scan3_one(int d) {
    if ((g_bm2[d >> 5] >> (d & 31)) & 1u) atomicAdd(&g_deg[d], 1);
}

__global__ void __launch_bounds__(NT, 1)
fused_kernel(const float* __restrict__ x,
             const int*   __restrict__ src,
             const int*   __restrict__ dst,
             int N, int E,
             const float* __restrict__ W1, const float* __restrict__ b1,
             const float* __restrict__ W2, const float* __restrict__ b2,
             const float* __restrict__ w_ih,
             const float* __restrict__ b_ih, const float* __restrict__ b_hh,
             const float* __restrict__ fc_w, const float* __restrict__ fc_b,
             float* __restrict__ out)
{
    __shared__ float sW1[IND * H];       // 32 KB
    __shared__ float sx[4][IND];         // x-column staging (4 nodes at once)
    __shared__ float sh[H];
    __shared__ float z[H], gates[4 * H], red[H];
    __shared__ float scof[256];
    __shared__ int   sspb[256];

    const int tid = threadIdx.x;
    const int gid = blockIdx.x * NT + tid;
    const int nth = NB * NT;

    // Preload W1 into shared (needed at phase 3).
    for (int k = tid; k < IND * H; k += NT) sW1[k] = W1[k];

    // ---------------- phase 0: init ----------------
    for (int i = gid; i < N; i += nth) { g_deg[i] = 0; g_flag1[i] = 0; g_flag2[i] = 0; }
    for (int i = gid; i < BMWORDS; i += nth) { g_bm1[i] = 0u; g_bm2[i] = 0u; }
    for (int i = gid; i < S1CAP * H; i += nth) ((float*)g_acc1)[i] = 0.0f;
    if (gid == 0) {
        g_cnt1 = 1; g_cnt2 = 1; g_cntE0 = 0; g_cntE1 = 0;
        g_s1[0] = 0; g_s2[0] = 0;
        g_flag1[0] = 1; g_flag2[0] = 1;
        g_bm1[0] = 1u; g_bm2[0] = 1u;
    }
    gridbar();

    const int E4 = E >> 2;
    const int4* d4 = (const int4*)dst;

    // ---------------- phase 1: dst==0 scan ----------------
    {
        int i = gid;
        for (; i + 3 * nth < E4; i += 4 * nth) {
            int4 a = d4[i], b = d4[i + nth], c = d4[i + 2 * nth], dd = d4[i + 3 * nth];
            scan1_one(src, a.x, 4*i+0); scan1_one(src, a.y, 4*i+1);
            scan1_one(src, a.z, 4*i+2); scan1_one(src, a.w, 4*i+3);
            int j1 = i + nth;
            scan1_one(src, b.x, 4*j1+0); scan1_one(src, b.y, 4*j1+1);
            scan1_one(src, b.z, 4*j1+2); scan1_one(src, b.w, 4*j1+3);
            int j2 = i + 2 * nth;
            scan1_one(src, c.x, 4*j2+0); scan1_one(src, c.y, 4*j2+1);
            scan1_one(src, c.z, 4*j2+2); scan1_one(src, c.w, 4*j2+3);
            int j3 = i + 3 * nth;
            scan1_one(src, dd.x, 4*j3+0); scan1_one(src, dd.y, 4*j3+1);
            scan1_one(src, dd.z, 4*j3+2); scan1_one(src, dd.w, 4*j3+3);
        }
        for (; i < E4; i += nth) {
            int4 a = d4[i];
            scan1_one(src, a.x, 4*i+0); scan1_one(src, a.y, 4*i+1);
            scan1_one(src, a.z, 4*i+2); scan1_one(src, a.w, 4*i+3);
        }
        for (int j = E4 * 4 + gid; j < E; j += nth) scan1_one(src, dst[j], j);
    }
    gridbar();

    // ---------------- phase 2: dst in S1 scan ----------------
    {
        int i = gid;
        for (; i + 3 * nth < E4; i += 4 * nth) {
            int4 a = d4[i], b = d4[i + nth], c = d4[i + 2 * nth], dd = d4[i + 3 * nth];
            scan2_one(src, a.x, 4*i+0); scan2_one(src, a.y, 4*i+1);
            scan2_one(src, a.z, 4*i+2); scan2_one(src, a.w, 4*i+3);
            int j1 = i + nth;
            scan2_one(src, b.x, 4*j1+0); scan2_one(src, b.y, 4*j1+1);
            scan2_one(src, b.z, 4*j1+2); scan2_one(src, b.w, 4*j1+3);
            int j2 = i + 2 * nth;
            scan2_one(src, c.x, 4*j2+0); scan2_one(src, c.y, 4*j2+1);
            scan2_one(src, c.z, 4*j2+2); scan2_one(src, c.w, 4*j2+3);
            int j3 = i + 3 * nth;
            scan2_one(src, dd.x, 4*j3+0); scan2_one(src, dd.y, 4*j3+1);
            scan2_one(src, dd.z, 4*j3+2); scan2_one(src, dd.w, 4*j3+3);
        }
        for (; i < E4; i += nth) {
            int4 a = d4[i];
            scan2_one(src, a.x, 4*i+0); scan2_one(src, a.y, 4*i+1);
            scan2_one(src, a.z, 4*i+2); scan2_one(src, a.w, 4*i+3);
        }
        for (int j = E4 * 4 + gid; j < E; j += nth) scan2_one(src, dst[j], j);
    }
    gridbar();

    // ---------------- phase 3: gated degree scan + hlin ----------------
    {
        int i = gid;
        for (; i + 3 * nth < E4; i += 4 * nth) {
            int4 a = d4[i], b = d4[i + nth], c = d4[i + 2 * nth], dd = d4[i + 3 * nth];
            scan3_one(a.x); scan3_one(a.y); scan3_one(a.z); scan3_one(a.w);
            scan3_one(b.x); scan3_one(b.y); scan3_one(b.z); scan3_one(b.w);
            scan3_one(c.x); scan3_one(c.y); scan3_one(c.z); scan3_one(c.w);
            scan3_one(dd.x); scan3_one(dd.y); scan3_one(dd.z); scan3_one(dd.w);
        }
        for (; i < E4; i += nth) {
            int4 a = d4[i];
            scan3_one(a.x); scan3_one(a.y); scan3_one(a.z); scan3_one(a.w);
        }
        for (int j = E4 * 4 + gid; j < E; j += nth) scan3_one(dst[j]);
    }
    // hlin: depends only on phase 2 results -> same phase as degree scan.
    {
        int m2 = g_cnt2; if (m2 > ECAP) m2 = ECAP;
        int g  = tid >> 7;
        int lt = tid & 127;
        for (int base = blockIdx.x * 4; base < m2; base += NB * 4) {
            int j = base + g;
            int u = (j < m2) ? g_s2[j] : -1;
            if (u >= 0) sx[g][lt] = __ldg(&x[(size_t)lt * N + u]);
            __syncthreads();
            if (u >= 0 && lt < H) {
                float acc = 0.0f;
                #pragma unroll
                for (int d = 0; d < IND; d++) acc += sx[g][d] * sW1[d * H + lt];
                g_hlin[j][lt] = acc;
            }
            __syncthreads();
        }
    }
    gridbar();

    // ---------------- phase 4: layer-1 aggregation (self + edges) ----------------
    {
        int m1 = g_cnt1; if (m1 > S1CAP) m1 = S1CAP;
        int sub = tid >> 6, tt = tid & 63;
        for (int j = blockIdx.x * 8 + sub; j < m1; j += NB * 8) {
            int u  = g_s1[j];
            float di = rsqrtf((float)g_deg[u] + 1.0f);
            int p2 = g_flag2[u] - 1;
            atomicAdd(&g_acc1[j][tt], di * di * g_hlin[p2][tt]);
        }
        int mE = g_cntE1; if (mE > ECAP) mE = ECAP;
        for (int e = blockIdx.x * 8 + sub; e < mE; e += NB * 8) {
            int2 ed = g_e1[e];
            int dp = g_flag1[ed.y] - 1;
            int sp = g_flag2[ed.x] - 1;
            float nrm = rsqrtf((float)g_deg[ed.x] + 1.0f) * rsqrtf((float)g_deg[ed.y] + 1.0f);
            atomicAdd(&g_acc1[dp][tt], nrm * g_hlin[sp][tt]);
        }
    }
    gridbar();

    // ---------------- phase 5: h2 = relu(acc1+b1) @ W2 ----------------
    {
        int m1 = g_cnt1; if (m1 > S1CAP) m1 = S1CAP;
        for (int j = blockIdx.x; j < m1; j += NB) {
            if (tid < H) sh[tid] = fmaxf(g_acc1[j][tid] + b1[tid], 0.0f);
            __syncthreads();
            if (tid < H) {
                float acc = 0.0f;
                #pragma unroll
                for (int h = 0; h < H; h++) acc += sh[h] * __ldg(&W2[h * H + tid]);
                g_h2[j][tid] = acc;
            }
            __syncthreads();
        }
    }
    gridbar();

    // ---------------- phase 6: node-0 layer-2 agg + LSTM + FC ----------------
    if (blockIdx.x == 0) {
        int m0 = g_cntE0; if (m0 > E0CAP) m0 = E0CAP;
        float d0 = rsqrtf((float)g_deg[0] + 1.0f);
        float zv = 0.0f;
        if (tid < H) zv = b2[tid] + d0 * d0 * g_h2[0][tid];
        for (int base = 0; base < m0; base += 256) {
            int k = base + tid;
            if (tid < 256 && k < m0) {
                int s = g_e0[k];
                scof[tid] = rsqrtf((float)g_deg[s] + 1.0f) * d0;
                sspb[tid] = g_flag1[s] - 1;
            }
            __syncthreads();
            int lim = m0 - base; if (lim > 256) lim = 256;
            if (tid < H) {
                for (int e = 0; e < lim; e++) zv += scof[e] * g_h2[sspb[e]][tid];
            }
            __syncthreads();
        }
        if (tid < H) z[tid] = zv;
        __syncthreads();
        if (tid < 4 * H) {
            float a = b_ih[tid] + b_hh[tid];
            #pragma unroll
            for (int h = 0; h < H; h++) a += __ldg(&w_ih[tid * H + h]) * z[h];
            gates[tid] = a;
        }
        __syncthreads();
        if (tid < H) {
            float ig = gates[tid];
            float gg = gates[2 * H + tid];
            float og = gates[3 * H + tid];
            float si = 1.0f / (1.0f + expf(-ig));
            float c  = si * tanhf(gg);
            float so = 1.0f / (1.0f + expf(-og));
            float hy = so * tanhf(c);
            red[tid] = hy * fc_w[tid];
        }
        __syncthreads();
        if (tid == 0) {
            float s = 0.0f;
            for (int k = 0; k < H; k++) s += red[k];
            out[0] = s + fc_b[0];
        }
    }
}

// ---------------------------------------------------------------------------
extern "C" void kernel_launch(void* const* d_in, const int* in_sizes, int n_in,
                              void* d_out, int out_size) {
    const float* x    = (const float*)d_in[0];
    const int*   ei   = (const int*)d_in[1];
    const float* W1   = (const float*)d_in[2];
    const float* b1   = (const float*)d_in[3];
    const float* W2   = (const float*)d_in[4];
    const float* b2   = (const float*)d_in[5];
    const float* w_ih = (const float*)d_in[6];
    // d_in[7] = w_hh (unused: h0 = 0)
    const float* b_ih = (const float*)d_in[8];
    const float* b_hh = (const float*)d_in[9];
    const float* fc_w = (const float*)d_in[10];
    const float* fc_b = (const float*)d_in[11];
    float* out = (float*)d_out;

    int N = in_sizes[0] / IND;
    int E = in_sizes[1] / 2;
    const int* src = ei;
    const int* dst = ei + E;

    fused_kernel<<<NB, NT>>>(x, src, dst, N, E, W1, b1, W2, b2,
                             w_ih, b_ih, b_hh, fc_w, fc_b, out);
}

// round 3
// speedup vs baseline: 1.1421x; 1.0413x over previous
#include <cuda_runtime.h>
#include <math.h>

// ---------------------------------------------------------------------------
// Single persistent kernel. Output depends only on the 2-hop in-neighborhood
// of node 0: S1 = in-neighbors of 0 (~32), S2 = in-neighbors of S1 (~1100).
// Phases (software grid barriers, 148 co-resident CTAs):
//   0: init flags/bitmaps
//   1: scan dst for dst==0        -> e0 list, S1 set           (ALU test)
//   2: scan dst, bm1 test (SMEM)  -> e1 list, S2 set
//   3: scan dst, bm2 test (SMEM)  -> deg ; then hlin = x[:,u]@W1 for u in S2
//   4: layer-1 aggregation into acc1 (self loops + e1 edges, atomics)
//   5: h2 = relu(acc1+b1) @ W2 for S1 nodes
//   6: block 0: layer-2 agg at node 0 -> LSTM -> FC -> out
// Key fix vs R2: bitmap probes moved from global (random, ~60 cyc/warp in
// L1tex wavefront replays) to shared memory (~3 cyc/warp).
// ---------------------------------------------------------------------------

#define NN_MAX   100000
#define IND      128
#define H        64
#define NB       148
#define NT       512
#define S1CAP    512
#define E0CAP    2048
#define ECAP     32768
#define BMWORDS  ((NN_MAX + 31) / 32)   // 3125

static __device__ int      g_deg[NN_MAX];
static __device__ int      g_flag1[NN_MAX];   // pos+1 in S1 (0 = not member)
static __device__ int      g_flag2[NN_MAX];   // pos+1 in S2
static __device__ unsigned g_bm1[BMWORDS];
static __device__ unsigned g_bm2[BMWORDS];
static __device__ int      g_s1[S1CAP];
static __device__ int      g_e0[E0CAP];       // src of edges with dst==0
static __device__ int      g_s2[ECAP];
static __device__ int2     g_e1[ECAP];        // edges with dst in S1
static __device__ int      g_cnt1, g_cnt2, g_cntE0, g_cntE1;
static __device__ float    g_hlin[ECAP][H];
static __device__ float    g_acc1[S1CAP][H];
static __device__ float    g_h2[S1CAP][H];
static __device__ unsigned g_barcnt = 0;
static __device__ unsigned g_sense  = 0;

// Software grid barrier with gpu-scope fence (store visibility + L1 inval).
__device__ __forceinline__ void gridbar() {
    __threadfence();
    __syncthreads();
    if (threadIdx.x == 0) {
        unsigned s = *((volatile unsigned*)&g_sense);
        if (atomicAdd(&g_barcnt, 1u) == NB - 1u) {
            atomicExch(&g_barcnt, 0u);
            __threadfence();
            atomicAdd(&g_sense, 1u);
        } else {
            while (*((volatile unsigned*)&g_sense) == s) { }
        }
        __threadfence();
    }
    __syncthreads();
}

__device__ __forceinline__ void scan1_one(const int* __restrict__ src, int d, int idx) {
    if (d == 0) {
        int s = __ldcg(&src[idx]);
        int p = atomicAdd(&g_cntE0, 1);
        if (p < E0CAP) g_e0[p] = s;
        if (atomicCAS(&g_flag1[s], 0, -1) == 0) {
            int q = atomicAdd(&g_cnt1, 1);
            if (q < S1CAP) g_s1[q] = s;
            g_flag1[s] = q + 1;
            atomicOr(&g_bm1[s >> 5], 1u << (s & 31));
            if (atomicCAS(&g_flag2[s], 0, -1) == 0) {
                int r = atomicAdd(&g_cnt2, 1);
                if (r < ECAP) g_s2[r] = s;
                g_flag2[s] = r + 1;
                atomicOr(&g_bm2[s >> 5], 1u << (s & 31));
            }
        }
    }
}

__device__ __forceinline__ void scan2_one(const unsigned* sbm,
                                          const int* __restrict__ src, int d, int idx) {
    if ((sbm[d >> 5] >> (d & 31)) & 1u) {
        int s = __ldcg(&src[idx]);
        int p = atomicAdd(&g_cntE1, 1);
        if (p < ECAP) g_e1[p] = make_int2(s, d);
        if (atomicCAS(&g_flag2[s], 0, -1) == 0) {
            int r = atomicAdd(&g_cnt2, 1);
            if (r < ECAP) g_s2[r] = s;
            g_flag2[s] = r + 1;
            atomicOr(&g_bm2[s >> 5], 1u << (s & 31));
        }
    }
}

__device__ __forceinline__ void scan3_one(const unsigned* sbm, int d) {
    if ((sbm[d >> 5] >> (d & 31)) & 1u) atomicAdd(&g_deg[d], 1);
}

__global__ void __launch_bounds__(NT, 1)
fused_kernel(const float* __restrict__ x,
             const int*   __restrict__ src,
             const int*   __restrict__ dst,
             int N, int E,
             const float* __restrict__ W1, const float* __restrict__ b1,
             const float* __restrict__ W2, const float* __restrict__ b2,
             const float* __restrict__ w_ih,
             const float* __restrict__ b_ih, const float* __restrict__ b_hh,
             const float* __restrict__ fc_w, const float* __restrict__ fc_b,
             float* __restrict__ out)
{
    __shared__ float sW1[IND * H];             // 32 KB, loaded once, used phase 3
    __shared__ union {
        unsigned bm[BMWORDS];                  // 12.5 KB, phases 2 & 3 (scan part)
        struct {
            float sx[4][IND];
            float sh[H];
            float z[H], gates[4 * H], red[H];
            float scof[256];
            int   sspb[256];
        } p;                                   // phases 3 (hlin), 5, 6
    } u;

    const int tid = threadIdx.x;
    const int gid = blockIdx.x * NT + tid;
    const int nth = NB * NT;

    for (int k = tid; k < IND * H; k += NT) sW1[k] = W1[k];

    // ---------------- phase 0: init ----------------
    for (int i = gid; i < N; i += nth) { g_flag1[i] = 0; g_flag2[i] = 0; }
    for (int i = gid; i < BMWORDS; i += nth) { g_bm1[i] = 0u; g_bm2[i] = 0u; }
    if (gid == 0) {
        g_cnt1 = 1; g_cnt2 = 1; g_cntE0 = 0; g_cntE1 = 0;
        g_s1[0] = 0; g_s2[0] = 0;
        g_flag1[0] = 1; g_flag2[0] = 1;
        g_bm1[0] = 1u; g_bm2[0] = 1u;
        g_deg[0] = 0;
    }
    gridbar();

    const int E4 = E >> 2;
    const int4* d4 = (const int4*)dst;

    // ---------------- phase 1: dst==0 scan (no bitmap) ----------------
    {
        int i = gid;
        for (; i + 7 * nth < E4; i += 8 * nth) {
            int4 v[8];
            #pragma unroll
            for (int b = 0; b < 8; b++) v[b] = __ldcg(&d4[i + b * nth]);
            #pragma unroll
            for (int b = 0; b < 8; b++) {
                int j = i + b * nth;
                scan1_one(src, v[b].x, 4*j+0); scan1_one(src, v[b].y, 4*j+1);
                scan1_one(src, v[b].z, 4*j+2); scan1_one(src, v[b].w, 4*j+3);
            }
        }
        for (; i < E4; i += nth) {
            int4 a = __ldcg(&d4[i]);
            scan1_one(src, a.x, 4*i+0); scan1_one(src, a.y, 4*i+1);
            scan1_one(src, a.z, 4*i+2); scan1_one(src, a.w, 4*i+3);
        }
        for (int j = E4 * 4 + gid; j < E; j += nth) scan1_one(src, __ldcg(&dst[j]), j);
    }
    gridbar();

    // ---------------- phase 2: bm1 (SMEM) test scan ----------------
    for (int k = tid; k < BMWORDS; k += NT) u.bm[k] = __ldcg(&g_bm1[k]);
    __syncthreads();
    {
        int i = gid;
        for (; i + 7 * nth < E4; i += 8 * nth) {
            int4 v[8];
            #pragma unroll
            for (int b = 0; b < 8; b++) v[b] = __ldcg(&d4[i + b * nth]);
            #pragma unroll
            for (int b = 0; b < 8; b++) {
                int j = i + b * nth;
                scan2_one(u.bm, src, v[b].x, 4*j+0); scan2_one(u.bm, src, v[b].y, 4*j+1);
                scan2_one(u.bm, src, v[b].z, 4*j+2); scan2_one(u.bm, src, v[b].w, 4*j+3);
            }
        }
        for (; i < E4; i += nth) {
            int4 a = __ldcg(&d4[i]);
            scan2_one(u.bm, src, a.x, 4*i+0); scan2_one(u.bm, src, a.y, 4*i+1);
            scan2_one(u.bm, src, a.z, 4*i+2); scan2_one(u.bm, src, a.w, 4*i+3);
        }
        for (int j = E4 * 4 + gid; j < E; j += nth) scan2_one(u.bm, src, __ldcg(&dst[j]), j);
    }
    gridbar();

    // ---------------- phase 3a: zero deg for S2 nodes ----------------
    int m2 = __ldcg(&g_cnt2); if (m2 > ECAP) m2 = ECAP;
    for (int j = gid; j < m2; j += nth) g_deg[__ldcg(&g_s2[j])] = 0;
    // zero acc1 rows for S1 nodes
    int m1 = __ldcg(&g_cnt1); if (m1 > S1CAP) m1 = S1CAP;
    for (int i = gid; i < m1 * H; i += nth) ((float*)g_acc1)[i] = 0.0f;
    gridbar();

    // ---------------- phase 3b: bm2 (SMEM) gated degree scan ----------------
    __syncthreads();
    for (int k = tid; k < BMWORDS; k += NT) u.bm[k] = __ldcg(&g_bm2[k]);
    __syncthreads();
    {
        int i = gid;
        for (; i + 7 * nth < E4; i += 8 * nth) {
            int4 v[8];
            #pragma unroll
            for (int b = 0; b < 8; b++) v[b] = __ldcg(&d4[i + b * nth]);
            #pragma unroll
            for (int b = 0; b < 8; b++) {
                scan3_one(u.bm, v[b].x); scan3_one(u.bm, v[b].y);
                scan3_one(u.bm, v[b].z); scan3_one(u.bm, v[b].w);
            }
        }
        for (; i < E4; i += nth) {
            int4 a = __ldcg(&d4[i]);
            scan3_one(u.bm, a.x); scan3_one(u.bm, a.y);
            scan3_one(u.bm, a.z); scan3_one(u.bm, a.w);
        }
        for (int j = E4 * 4 + gid; j < E; j += nth) scan3_one(u.bm, __ldcg(&dst[j]));
    }
    // ---------------- phase 3c: hlin = x[:,u] @ W1 (bm no longer needed) ----
    __syncthreads();
    {
        int g  = tid >> 7;
        int lt = tid & 127;
        for (int base = blockIdx.x * 4; base < m2; base += NB * 4) {
            int j = base + g;
            int un = (j < m2) ? __ldcg(&g_s2[j]) : -1;
            if (un >= 0) u.p.sx[g][lt] = __ldcg(&x[(size_t)lt * N + un]);
            __syncthreads();
            if (un >= 0 && lt < H) {
                float acc = 0.0f;
                #pragma unroll
                for (int d = 0; d < IND; d++) acc += u.p.sx[g][d] * sW1[d * H + lt];
                g_hlin[j][lt] = acc;
            }
            __syncthreads();
        }
    }
    gridbar();

    // ---------------- phase 4: layer-1 aggregation ----------------
    {
        int sub = tid >> 6, tt = tid & 63;
        for (int j = blockIdx.x * 8 + sub; j < m1; j += NB * 8) {
            int un  = __ldcg(&g_s1[j]);
            float di = rsqrtf((float)__ldcg(&g_deg[un]) + 1.0f);
            int p2 = __ldcg(&g_flag2[un]) - 1;
            atomicAdd(&g_acc1[j][tt], di * di * __ldcg(&g_hlin[p2][tt]));
        }
        int mE = __ldcg(&g_cntE1); if (mE > ECAP) mE = ECAP;
        for (int e = blockIdx.x * 8 + sub; e < mE; e += NB * 8) {
            int2 ed; ed.x = __ldcg(&g_e1[e].x); ed.y = __ldcg(&g_e1[e].y);
            int dp = __ldcg(&g_flag1[ed.y]) - 1;
            int sp = __ldcg(&g_flag2[ed.x]) - 1;
            float nrm = rsqrtf((float)__ldcg(&g_deg[ed.x]) + 1.0f)
                      * rsqrtf((float)__ldcg(&g_deg[ed.y]) + 1.0f);
            atomicAdd(&g_acc1[dp][tt], nrm * __ldcg(&g_hlin[sp][tt]));
        }
    }
    gridbar();

    // ---------------- phase 5: h2 = relu(acc1+b1) @ W2 ----------------
    {
        for (int j = blockIdx.x; j < m1; j += NB) {
            if (tid < H) u.p.sh[tid] = fmaxf(__ldcg(&g_acc1[j][tid]) + b1[tid], 0.0f);
            __syncthreads();
            if (tid < H) {
                float acc = 0.0f;
                #pragma unroll
                for (int h = 0; h < H; h++) acc += u.p.sh[h] * __ldg(&W2[h * H + tid]);
                g_h2[j][tid] = acc;
            }
            __syncthreads();
        }
    }
    gridbar();

    // ---------------- phase 6: node-0 layer-2 agg + LSTM + FC ----------------
    if (blockIdx.x == 0) {
        int m0 = __ldcg(&g_cntE0); if (m0 > E0CAP) m0 = E0CAP;
        float d0 = rsqrtf((float)__ldcg(&g_deg[0]) + 1.0f);
        float zv = 0.0f;
        if (tid < H) zv = b2[tid] + d0 * d0 * __ldcg(&g_h2[0][tid]);
        for (int base = 0; base < m0; base += 256) {
            int k = base + tid;
            if (tid < 256 && k < m0) {
                int s = __ldcg(&g_e0[k]);
                u.p.scof[tid] = rsqrtf((float)__ldcg(&g_deg[s]) + 1.0f) * d0;
                u.p.sspb[tid] = __ldcg(&g_flag1[s]) - 1;
            }
            __syncthreads();
            int lim = m0 - base; if (lim > 256) lim = 256;
            if (tid < H) {
                for (int e = 0; e < lim; e++)
                    zv += u.p.scof[e] * __ldcg(&g_h2[u.p.sspb[e]][tid]);
            }
            __syncthreads();
        }
        if (tid < H) u.p.z[tid] = zv;
        __syncthreads();
        if (tid < 4 * H) {
            float a = b_ih[tid] + b_hh[tid];
            #pragma unroll
            for (int h = 0; h < H; h++) a += __ldg(&w_ih[tid * H + h]) * u.p.z[h];
            u.p.gates[tid] = a;
        }
        __syncthreads();
        if (tid < H) {
            float ig = u.p.gates[tid];
            float gg = u.p.gates[2 * H + tid];
            float og = u.p.gates[3 * H + tid];
            float si = 1.0f / (1.0f + expf(-ig));
            float c  = si * tanhf(gg);
            float so = 1.0f / (1.0f + expf(-og));
            float hy = so * tanhf(c);
            u.p.red[tid] = hy * fc_w[tid];
        }
        __syncthreads();
        if (tid == 0) {
            float s = 0.0f;
            for (int k = 0; k < H; k++) s += u.p.red[k];
            out[0] = s + fc_b[0];
        }
    }
}

// ---------------------------------------------------------------------------
extern "C" void kernel_launch(void* const* d_in, const int* in_sizes, int n_in,
                              void* d_out, int out_size) {
    const float* x    = (const float*)d_in[0];
    const int*   ei   = (const int*)d_in[1];
    const float* W1   = (const float*)d_in[2];
    const float* b1   = (const float*)d_in[3];
    const float* W2   = (const float*)d_in[4];
    const float* b2   = (const float*)d_in[5];
    const float* w_ih = (const float*)d_in[6];
    // d_in[7] = w_hh (unused: h0 = 0)
    const float* b_ih = (const float*)d_in[8];
    const float* b_hh = (const float*)d_in[9];
    const float* fc_w = (const float*)d_in[10];
    const float* fc_b = (const float*)d_in[11];
    float* out = (float*)d_out;

    int N = in_sizes[0] / IND;
    int E = in_sizes[1] / 2;
    const int* src = ei;
    const int* dst = ei + E;

    fused_kernel<<<NB, NT>>>(x, src, dst, N, E, W1, b1, W2, b2,
                             w_ih, b_ih, b_hh, fc_w, fc_b, out);
}

// round 6
// speedup vs baseline: 1.3366x; 1.1702x over previous
#include <cuda_runtime.h>
#include <math.h>

// ---------------------------------------------------------------------------
// GCN(2)->node0->LSTM->FC. Only the 2-hop in-neighborhood of node 0 matters:
// S1 = in-neighbors of 0 (~32), S2 = in-neighbors of S1 (~1100).
// Six kernels (launch edges = barriers, per-launch L1 flush = coherence):
//   1 init   : zero flags/bitmaps/deg/acc, seed node 0
//   2 scan1  : dst==0            -> e0 list, S1 set, bm1
//   3 scan2  : dst in bm1 (SMEM) -> e1 list, S2 set, bm2
//   4 scan3h : dst in bm2 (SMEM) -> deg  ; then hlin = x[:,u]@W1, u in S2
//   5 agg    : layer-1 aggregation into acc1 (self loops + e1, atomics)
//   6 tail   : one block: h2 = relu(acc1+b1)@W2 ; node-0 layer-2 agg ;
//              LSTM single step ; FC -> out
// ---------------------------------------------------------------------------

#define NN_MAX   100000
#define IND      128
#define H        64
#define S1CAP    512
#define E0CAP    2048
#define ECAP     32768
#define BMW      ((NN_MAX + 31) / 32)   // 3125 words = 12.5 KB
#define SCAN_B   296
#define SCAN_T   512

static __device__ int      g_deg[NN_MAX];
static __device__ int      g_flag1[NN_MAX];   // pos+1 in S1 (0 = not member)
static __device__ int      g_flag2[NN_MAX];   // pos+1 in S2
static __device__ unsigned g_bm1[BMW];
static __device__ unsigned g_bm2[BMW];
static __device__ int      g_s1[S1CAP];
static __device__ int      g_e0[E0CAP];       // src of edges with dst==0
static __device__ int      g_s2[ECAP];
static __device__ int2     g_e1[ECAP];        // edges with dst in S1
static __device__ int      g_cnt1, g_cnt2, g_cntE0, g_cntE1;
static __device__ float    g_hlin[ECAP][H];
static __device__ float    g_acc1[S1CAP][H];
static __device__ float    g_h2[S1CAP][H];

// ---------------------------------------------------------------------------
__global__ void k_init(int N) {
    int i = blockIdx.x * blockDim.x + threadIdx.x;
    int nth = gridDim.x * blockDim.x;
    for (int k = i; k < N; k += nth) { g_flag1[k] = 0; g_flag2[k] = 0; g_deg[k] = 0; }
    for (int k = i; k < BMW; k += nth) { g_bm1[k] = 0u; g_bm2[k] = 0u; }
    for (int k = i; k < S1CAP * H; k += nth) ((float*)g_acc1)[k] = 0.0f;
    if (i == 0) {
        g_cnt1 = 1; g_cnt2 = 1; g_cntE0 = 0; g_cntE1 = 0;
        g_s1[0] = 0; g_s2[0] = 0;
        g_flag1[0] = 1; g_flag2[0] = 1;
        g_bm1[0] = 1u; g_bm2[0] = 1u;
    }
}

// ---------------------------------------------------------------------------
__device__ __forceinline__ void s1_one(const int* __restrict__ src, int d, int idx) {
    if (d == 0) {
        int s = __ldcg(&src[idx]);
        int p = atomicAdd(&g_cntE0, 1);
        if (p < E0CAP) g_e0[p] = s;
        if (atomicCAS(&g_flag1[s], 0, -1) == 0) {
            int q = atomicAdd(&g_cnt1, 1);
            if (q < S1CAP) g_s1[q] = s;
            g_flag1[s] = q + 1;
            atomicOr(&g_bm1[s >> 5], 1u << (s & 31));
            if (atomicCAS(&g_flag2[s], 0, -1) == 0) {
                int r = atomicAdd(&g_cnt2, 1);
                if (r < ECAP) g_s2[r] = s;
                g_flag2[s] = r + 1;
                atomicOr(&g_bm2[s >> 5], 1u << (s & 31));
            }
        }
    }
}

__global__ void __launch_bounds__(SCAN_T)
k_scan1(const int* __restrict__ src, const int* __restrict__ dst, int E) {
    int gid = blockIdx.x * SCAN_T + threadIdx.x;
    int nth = SCAN_B * SCAN_T;
    int E4 = E >> 2;
    const int4* d4 = (const int4*)dst;
    int i = gid;
    for (; i + 3 * nth < E4; i += 4 * nth) {
        int4 v0 = __ldcg(&d4[i]);
        int4 v1 = __ldcg(&d4[i + nth]);
        int4 v2 = __ldcg(&d4[i + 2 * nth]);
        int4 v3 = __ldcg(&d4[i + 3 * nth]);
        int j;
        j = i;           s1_one(src, v0.x, 4*j); s1_one(src, v0.y, 4*j+1); s1_one(src, v0.z, 4*j+2); s1_one(src, v0.w, 4*j+3);
        j = i + nth;     s1_one(src, v1.x, 4*j); s1_one(src, v1.y, 4*j+1); s1_one(src, v1.z, 4*j+2); s1_one(src, v1.w, 4*j+3);
        j = i + 2 * nth; s1_one(src, v2.x, 4*j); s1_one(src, v2.y, 4*j+1); s1_one(src, v2.z, 4*j+2); s1_one(src, v2.w, 4*j+3);
        j = i + 3 * nth; s1_one(src, v3.x, 4*j); s1_one(src, v3.y, 4*j+1); s1_one(src, v3.z, 4*j+2); s1_one(src, v3.w, 4*j+3);
    }
    for (; i < E4; i += nth) {
        int4 v = __ldcg(&d4[i]);
        s1_one(src, v.x, 4*i); s1_one(src, v.y, 4*i+1); s1_one(src, v.z, 4*i+2); s1_one(src, v.w, 4*i+3);
    }
    for (int j = (E4 << 2) + gid; j < E; j += nth) s1_one(src, __ldcg(&dst[j]), j);
}

// ---------------------------------------------------------------------------
__device__ __forceinline__ void s2_one(const unsigned* sbm,
                                       const int* __restrict__ src, int d, int idx) {
    if ((sbm[d >> 5] >> (d & 31)) & 1u) {
        int s = __ldcg(&src[idx]);
        int p = atomicAdd(&g_cntE1, 1);
        if (p < ECAP) g_e1[p] = make_int2(s, d);
        if (atomicCAS(&g_flag2[s], 0, -1) == 0) {
            int r = atomicAdd(&g_cnt2, 1);
            if (r < ECAP) g_s2[r] = s;
            g_flag2[s] = r + 1;
            atomicOr(&g_bm2[s >> 5], 1u << (s & 31));
        }
    }
}

__global__ void __launch_bounds__(SCAN_T)
k_scan2(const int* __restrict__ src, const int* __restrict__ dst, int E) {
    __shared__ unsigned sbm[BMW];
    for (int k = threadIdx.x; k < BMW; k += SCAN_T) sbm[k] = __ldg(&g_bm1[k]);
    __syncthreads();
    int gid = blockIdx.x * SCAN_T + threadIdx.x;
    int nth = SCAN_B * SCAN_T;
    int E4 = E >> 2;
    const int4* d4 = (const int4*)dst;
    int i = gid;
    for (; i + 3 * nth < E4; i += 4 * nth) {
        int4 v0 = __ldcg(&d4[i]);
        int4 v1 = __ldcg(&d4[i + nth]);
        int4 v2 = __ldcg(&d4[i + 2 * nth]);
        int4 v3 = __ldcg(&d4[i + 3 * nth]);
        int j;
        j = i;           s2_one(sbm, src, v0.x, 4*j); s2_one(sbm, src, v0.y, 4*j+1); s2_one(sbm, src, v0.z, 4*j+2); s2_one(sbm, src, v0.w, 4*j+3);
        j = i + nth;     s2_one(sbm, src, v1.x, 4*j); s2_one(sbm, src, v1.y, 4*j+1); s2_one(sbm, src, v1.z, 4*j+2); s2_one(sbm, src, v1.w, 4*j+3);
        j = i + 2 * nth; s2_one(sbm, src, v2.x, 4*j); s2_one(sbm, src, v2.y, 4*j+1); s2_one(sbm, src, v2.z, 4*j+2); s2_one(sbm, src, v2.w, 4*j+3);
        j = i + 3 * nth; s2_one(sbm, src, v3.x, 4*j); s2_one(sbm, src, v3.y, 4*j+1); s2_one(sbm, src, v3.z, 4*j+2); s2_one(sbm, src, v3.w, 4*j+3);
    }
    for (; i < E4; i += nth) {
        int4 v = __ldcg(&d4[i]);
        s2_one(sbm, src, v.x, 4*i); s2_one(sbm, src, v.y, 4*i+1); s2_one(sbm, src, v.z, 4*i+2); s2_one(sbm, src, v.w, 4*i+3);
    }
    for (int j = (E4 << 2) + gid; j < E; j += nth) {
        int d = __ldcg(&dst[j]);
        s2_one(sbm, src, d, j);
    }
}

// ---------------------------------------------------------------------------
// Degree scan (bm2-gated) + hlin = x[:,u] @ W1 for u in S2. Independent work
// (both depend only on scan2 results) -> fused, no internal grid sync needed.
__global__ void __launch_bounds__(SCAN_T)
k_scan3_hlin(const int* __restrict__ dst, int E,
             const float* __restrict__ x, const float* __restrict__ W1, int N) {
    __shared__ unsigned sbm[BMW];       // 12.5 KB
    __shared__ float    sW1[IND * H];   // 32 KB
    __shared__ float    sx[4][IND];     // 2 KB
    for (int k = threadIdx.x; k < BMW; k += SCAN_T) sbm[k] = __ldg(&g_bm2[k]);
    for (int k = threadIdx.x; k < IND * H; k += SCAN_T) sW1[k] = W1[k];
    __syncthreads();

    int gid = blockIdx.x * SCAN_T + threadIdx.x;
    int nth = SCAN_B * SCAN_T;
    int E4 = E >> 2;
    const int4* d4 = (const int4*)dst;
    int i = gid;
    for (; i + 3 * nth < E4; i += 4 * nth) {
        int4 v0 = __ldcg(&d4[i]);
        int4 v1 = __ldcg(&d4[i + nth]);
        int4 v2 = __ldcg(&d4[i + 2 * nth]);
        int4 v3 = __ldcg(&d4[i + 3 * nth]);
        #define S3(dd) if ((sbm[(dd) >> 5] >> ((dd) & 31)) & 1u) atomicAdd(&g_deg[dd], 1)
        S3(v0.x); S3(v0.y); S3(v0.z); S3(v0.w);
        S3(v1.x); S3(v1.y); S3(v1.z); S3(v1.w);
        S3(v2.x); S3(v2.y); S3(v2.z); S3(v2.w);
        S3(v3.x); S3(v3.y); S3(v3.z); S3(v3.w);
    }
    for (; i < E4; i += nth) {
        int4 v = __ldcg(&d4[i]);
        S3(v.x); S3(v.y); S3(v.z); S3(v.w);
    }
    for (int j = (E4 << 2) + gid; j < E; j += nth) { int dd = __ldcg(&dst[j]); S3(dd); }
    #undef S3

    // hlin part: 4 nodes per block concurrently (128 threads each stage one
    // x-column in parallel; 64 of them then do the smem dot product).
    __syncthreads();
    int m2 = g_cnt2; if (m2 > ECAP) m2 = ECAP;
    int g  = threadIdx.x >> 7;
    int lt = threadIdx.x & 127;
    for (int base = blockIdx.x * 4; base < m2; base += SCAN_B * 4) {
        int j = base + g;
        int u = (j < m2) ? g_s2[j] : -1;
        if (u >= 0) sx[g][lt] = __ldg(&x[(size_t)lt * N + u]);
        __syncthreads();
        if (u >= 0 && lt < H) {
            float acc = 0.0f;
            #pragma unroll
            for (int d = 0; d < IND; d++) acc += sx[g][d] * sW1[d * H + lt];
            g_hlin[j][lt] = acc;
        }
        __syncthreads();
    }
}

// ---------------------------------------------------------------------------
// Layer-1 aggregation: self loops for S1 nodes + e1 edge scatter.
__global__ void k_agg(void) {
    int sub = threadIdx.x >> 6;          // 4 groups of 64 per block
    int tt  = threadIdx.x & 63;
    int ng  = gridDim.x * 4;
    int gi  = blockIdx.x * 4 + sub;
    int m1 = g_cnt1; if (m1 > S1CAP) m1 = S1CAP;
    for (int j = gi; j < m1; j += ng) {
        int u  = g_s1[j];
        float di = rsqrtf((float)g_deg[u] + 1.0f);
        int p2 = g_flag2[u] - 1;
        atomicAdd(&g_acc1[j][tt], di * di * g_hlin[p2][tt]);
    }
    int mE = g_cntE1; if (mE > ECAP) mE = ECAP;
    for (int e = gi; e < mE; e += ng) {
        int2 ed = g_e1[e];
        int dp = g_flag1[ed.y] - 1;
        int sp = g_flag2[ed.x] - 1;
        float nrm = rsqrtf((float)g_deg[ed.x] + 1.0f) * rsqrtf((float)g_deg[ed.y] + 1.0f);
        atomicAdd(&g_acc1[dp][tt], nrm * g_hlin[sp][tt]);
    }
}

// ---------------------------------------------------------------------------
// Single block: h2 for all S1 nodes, node-0 layer-2 aggregation, LSTM, FC.
__global__ void __launch_bounds__(512)
k_tail(const float* __restrict__ b1, const float* __restrict__ W2,
       const float* __restrict__ b2, const float* __restrict__ w_ih,
       const float* __restrict__ b_ih, const float* __restrict__ b_hh,
       const float* __restrict__ fc_w, const float* __restrict__ fc_b,
       float* __restrict__ out) {
    __shared__ float sW2[H * H];        // 16 KB
    __shared__ float h1buf[8][H];       // 2 KB
    __shared__ float z[H], gates[4 * H], red[H];
    __shared__ float scof[256];
    __shared__ int   sspb[256];

    int tid = threadIdx.x;
    for (int k = tid; k < H * H; k += 512) sW2[k] = W2[k];
    __syncthreads();

    int m1 = g_cnt1; if (m1 > S1CAP) m1 = S1CAP;
    int sub = tid >> 6, tt = tid & 63;
    for (int j0 = 0; j0 < m1; j0 += 8) {
        int j = j0 + sub;
        if (j < m1) h1buf[sub][tt] = fmaxf(g_acc1[j][tt] + b1[tt], 0.0f);
        __syncthreads();
        if (j < m1) {
            float acc = 0.0f;
            #pragma unroll
            for (int h = 0; h < H; h++) acc += h1buf[sub][h] * sW2[h * H + tt];
            g_h2[j][tt] = acc;
        }
        __syncthreads();
    }

    // node-0 layer-2 aggregation
    int m0 = g_cntE0; if (m0 > E0CAP) m0 = E0CAP;
    float d0 = rsqrtf((float)g_deg[0] + 1.0f);
    float zv = 0.0f;
    if (tid < H) zv = b2[tid] + d0 * d0 * g_h2[0][tid];
    for (int base = 0; base < m0; base += 256) {
        int k = base + tid;
        if (tid < 256 && k < m0) {
            int s = g_e0[k];
            scof[tid] = rsqrtf((float)g_deg[s] + 1.0f) * d0;
            sspb[tid] = g_flag1[s] - 1;
        }
        __syncthreads();
        int lim = m0 - base; if (lim > 256) lim = 256;
        if (tid < H)
            for (int e = 0; e < lim; e++) zv += scof[e] * g_h2[sspb[e]][tid];
        __syncthreads();
    }
    if (tid < H) z[tid] = zv;
    __syncthreads();

    if (tid < 4 * H) {
        float a = b_ih[tid] + b_hh[tid];
        #pragma unroll
        for (int h = 0; h < H; h++) a += __ldg(&w_ih[tid * H + h]) * z[h];
        gates[tid] = a;
    }
    __syncthreads();
    if (tid < H) {
        float ig = gates[tid];
        float gg = gates[2 * H + tid];
        float og = gates[3 * H + tid];
        float si = 1.0f / (1.0f + expf(-ig));
        float c  = si * tanhf(gg);
        float so = 1.0f / (1.0f + expf(-og));
        float hy = so * tanhf(c);
        red[tid] = hy * fc_w[tid];
    }
    __syncthreads();
    if (tid == 0) {
        float s = 0.0f;
        for (int k = 0; k < H; k++) s += red[k];
        out[0] = s + fc_b[0];
    }
}

// ---------------------------------------------------------------------------
extern "C" void kernel_launch(void* const* d_in, const int* in_sizes, int n_in,
                              void* d_out, int out_size) {
    const float* x    = (const float*)d_in[0];
    const int*   ei   = (const int*)d_in[1];
    const float* W1   = (const float*)d_in[2];
    const float* b1   = (const float*)d_in[3];
    const float* W2   = (const float*)d_in[4];
    const float* b2   = (const float*)d_in[5];
    const float* w_ih = (const float*)d_in[6];
    // d_in[7] = w_hh (unused: h0 = c0 = 0)
    const float* b_ih = (const float*)d_in[8];
    const float* b_hh = (const float*)d_in[9];
    const float* fc_w = (const float*)d_in[10];
    const float* fc_b = (const float*)d_in[11];
    float* out = (float*)d_out;

    int N = in_sizes[0] / IND;
    int E = in_sizes[1] / 2;
    const int* src = ei;
    const int* dst = ei + E;

    k_init<<<200, 512>>>(N);
    k_scan1<<<SCAN_B, SCAN_T>>>(src, dst, E);
    k_scan2<<<SCAN_B, SCAN_T>>>(src, dst, E);
    k_scan3_hlin<<<SCAN_B, SCAN_T>>>(dst, E, x, W1, N);
    k_agg<<<296, 256>>>();
    k_tail<<<1, 512>>>(b1, W2, b2, w_ih, b_ih, b_hh, fc_w, fc_b, out);
}